// round 4
// baseline (speedup 1.0000x reference)
#include <cuda_runtime.h>
#include <cuda_fp16.h>
#include <cstdint>
#include <cstddef>

// ============================================================================
// BinaryDense: out[8192,2048] = X[8192,2048](f32) @ binarize(W)[2048,2048]
//   binarize: w < 0 -> 0.0, w >= 0 -> 1.0   (exact in fp16)
//
// Toolchain reality (R1): ptxas target is plain sm_100 -> no tcgen05/TMEM.
// Path: prepass (X->fp16, W->binarized fp16 transposed), then sm_80-class
// HMMA GEMM: cp.async 4-stage pipeline + ldmatrix + mma.sync.m16n8k16,
// fp32 accumulation. All instructions are baseline sm_80/90 features.
// ============================================================================

static constexpr int Mdim = 8192;
static constexpr int Ndim = 2048;
static constexpr int Kdim = 2048;

static constexpr int BM = 128;
static constexpr int BN = 128;
static constexpr int BK = 64;                 // fp16: 128B rows
static constexpr int STAGES = 4;
static constexpr int NCHUNKS = Kdim / BK;     // 32
static constexpr int A_BYTES = BM * BK * 2;   // 16 KB
static constexpr int B_BYTES = BN * BK * 2;   // 16 KB
static constexpr int STAGE_BYTES = A_BYTES + B_BYTES;       // 32 KB
static constexpr int SMEM_SIZE = STAGES * STAGE_BYTES;      // 128 KB

// Allocation-free scratch (40 MB)
__device__ __align__(1024) __half g_Xh[(size_t)Mdim * Kdim]; // X fp16 [M,K]
__device__ __align__(1024) __half g_Wt[(size_t)Ndim * Kdim]; // bin(W)^T fp16 [N,K]

// ============================ helpers =======================================

__device__ __forceinline__ uint32_t smem_u32(const void* p) {
    uint32_t a;
    asm("{ .reg .u64 t; cvta.to.shared.u64 t, %1; cvt.u32.u64 %0, t; }"
        : "=r"(a) : "l"(p));
    return a;
}

__device__ __forceinline__ void cp_async16(uint32_t dst, const void* src) {
    asm volatile("cp.async.cg.shared.global [%0], [%1], 16;"
                 :: "r"(dst), "l"(src) : "memory");
}

__device__ __forceinline__ void cp_commit() {
    asm volatile("cp.async.commit_group;" ::: "memory");
}

template <int N>
__device__ __forceinline__ void cp_wait() {
    asm volatile("cp.async.wait_group %0;" :: "n"(N) : "memory");
}

__device__ __forceinline__ void ldsm_x4(uint32_t& r0, uint32_t& r1,
                                        uint32_t& r2, uint32_t& r3, uint32_t addr) {
    asm volatile("ldmatrix.sync.aligned.m8n8.x4.shared.b16 {%0,%1,%2,%3}, [%4];"
                 : "=r"(r0), "=r"(r1), "=r"(r2), "=r"(r3) : "r"(addr));
}

__device__ __forceinline__ void mma16816(float* c, const uint32_t* a,
                                         uint32_t b0, uint32_t b1) {
    asm volatile(
        "mma.sync.aligned.m16n8k16.row.col.f32.f16.f16.f32 "
        "{%0,%1,%2,%3}, {%4,%5,%6,%7}, {%8,%9}, {%0,%1,%2,%3};"
        : "+f"(c[0]), "+f"(c[1]), "+f"(c[2]), "+f"(c[3])
        : "r"(a[0]), "r"(a[1]), "r"(a[2]), "r"(a[3]), "r"(b0), "r"(b1));
}

// ============================ prepass kernels ===============================

__global__ void xconv_kernel(const float4* __restrict__ x, uint2* __restrict__ xh, int n4) {
    int i = blockIdx.x * blockDim.x + threadIdx.x;
    if (i < n4) {
        float4 v = x[i];
        __half2 a = __floats2half2_rn(v.x, v.y);
        __half2 b = __floats2half2_rn(v.z, v.w);
        uint2 u;
        u.x = *reinterpret_cast<const uint32_t*>(&a);
        u.y = *reinterpret_cast<const uint32_t*>(&b);
        xh[i] = u;
    }
}

// W [K,N] fp32 -> binarized W^T [N,K] fp16, tiled transpose
__global__ void wbin_kernel(const float* __restrict__ w, __half* __restrict__ wt) {
    __shared__ __half tile[32][33];
    int n0 = blockIdx.x * 32, k0 = blockIdx.y * 32;
    int tx = threadIdx.x, ty = threadIdx.y;
    #pragma unroll
    for (int i = 0; i < 32; i += 8) {
        float v = w[(size_t)(k0 + ty + i) * Ndim + (n0 + tx)];
        tile[ty + i][tx] = (v < 0.0f) ? __float2half(0.0f) : __float2half(1.0f);
    }
    __syncthreads();
    #pragma unroll
    for (int i = 0; i < 32; i += 8) {
        wt[(size_t)(n0 + ty + i) * Kdim + (k0 + tx)] = tile[tx][ty + i];
    }
}

// ============================ main GEMM kernel ==============================
//
// 256 threads = 8 warps as (wm 2) x (wn 4); warp tile 64m x 32n.
// Smem tiles: A [128][64] fp16 (128B rows), B [128][64] fp16 (row = n).
// 16B-granularity XOR swizzle: byte_off ^ ((row & 7) << 4)  (bits disjoint).

__device__ __forceinline__ void load_stage(
    int stage, int chunk, int mt, int nt, uint32_t sb, int tid)
{
    const uint32_t a_base = sb + stage * STAGE_BYTES;
    const uint32_t b_base = a_base + A_BYTES;
    const int m0 = mt * BM, n0 = nt * BN, k0 = chunk * BK;
    #pragma unroll
    for (int i = 0; i < 4; i++) {
        int id = tid + 256 * i;              // 0..1023
        int row = id >> 3, ch = id & 7;      // 8 x 16B chunks per 128B row
        uint32_t dst = a_base + row * 128 + ((ch * 16) ^ ((row & 7) << 4));
        cp_async16(dst, g_Xh + (size_t)(m0 + row) * Kdim + k0 + ch * 8);
    }
    #pragma unroll
    for (int i = 0; i < 4; i++) {
        int id = tid + 256 * i;
        int row = id >> 3, ch = id & 7;
        uint32_t dst = b_base + row * 128 + ((ch * 16) ^ ((row & 7) << 4));
        cp_async16(dst, g_Wt + (size_t)(n0 + row) * Kdim + k0 + ch * 8);
    }
}

__global__ void __launch_bounds__(256, 1) hgemm_kernel(float* __restrict__ out)
{
    extern __shared__ __align__(1024) char smem[];
    const uint32_t sb = smem_u32(smem);
    const int tid = threadIdx.x;
    const int wid = tid >> 5;
    const int lane = tid & 31;

    // 16 consecutive CTAs share the same A tile; all 16 B tiles (8 MB) stay
    // L2-resident -> HBM traffic ~ single pass of A + B + out.
    const int mt = blockIdx.x >> 4;
    const int nt = blockIdx.x & 15;

    const int wm = wid & 1;   // 0..1 -> 64-row halves
    const int wn = wid >> 1;  // 0..3 -> 32-col quarters

    float acc[4][4][4];
    #pragma unroll
    for (int i = 0; i < 4; i++)
        #pragma unroll
        for (int j = 0; j < 4; j++)
            #pragma unroll
            for (int q = 0; q < 4; q++) acc[i][j][q] = 0.0f;

    // ---- prologue: fill STAGES-1 stages ----
    #pragma unroll
    for (int s = 0; s < STAGES - 1; s++) {
        load_stage(s, s, mt, nt, sb, tid);
        cp_commit();
    }

    const int lrow = lane & 15;          // ldmatrix row within 16
    const int lhi  = lane >> 4;          // k-half selector (0/1)

    for (int c = 0; c < NCHUNKS; c++) {
        const int s = c & (STAGES - 1);
        cp_wait<STAGES - 2>();           // stage s resident
        __syncthreads();                 // + all warps done with stage (c-1)&3

        const int nc = c + (STAGES - 1);
        if (nc < NCHUNKS) load_stage(nc & (STAGES - 1), nc, mt, nt, sb, tid);
        cp_commit();                     // one group per iteration (may be empty)

        const uint32_t a_base = sb + s * STAGE_BYTES;
        const uint32_t b_base = a_base + A_BYTES;

        #pragma unroll
        for (int kk = 0; kk < BK / 16; kk++) {
            // A fragments: 4 x m16 tiles
            uint32_t afr[4][4];
            #pragma unroll
            for (int mf = 0; mf < 4; mf++) {
                int row = wm * 64 + mf * 16 + lrow;
                uint32_t addr = a_base + row * 128 +
                                ((kk * 32 + lhi * 16) ^ ((row & 7) << 4));
                ldsm_x4(afr[mf][0], afr[mf][1], afr[mf][2], afr[mf][3], addr);
            }
            // B fragments: 2 x n16 tiles (each = 2 n8 mma frags)
            uint32_t bfr[2][4];
            #pragma unroll
            for (int p = 0; p < 2; p++) {
                int row = wn * 32 + p * 16 + lrow;   // row = n index
                uint32_t addr = b_base + row * 128 +
                                ((kk * 32 + lhi * 16) ^ ((row & 7) << 4));
                ldsm_x4(bfr[p][0], bfr[p][1], bfr[p][2], bfr[p][3], addr);
            }
            #pragma unroll
            for (int mf = 0; mf < 4; mf++) {
                #pragma unroll
                for (int p = 0; p < 2; p++) {
                    // n-frag 2p  : b = {bfr[p][0], bfr[p][2]}
                    // n-frag 2p+1: b = {bfr[p][1], bfr[p][3]}
                    mma16816(acc[mf][2 * p],     afr[mf], bfr[p][0], bfr[p][2]);
                    mma16816(acc[mf][2 * p + 1], afr[mf], bfr[p][1], bfr[p][3]);
                }
            }
        }
        __syncthreads();                 // compute done before stage reuse
    }

    // ---- epilogue: direct float2 stores ----
    const int qrow = lane >> 2;          // 0..7
    const int qcol = lane & 3;           // 0..3
    #pragma unroll
    for (int mf = 0; mf < 4; mf++) {
        const int mrow = mt * BM + wm * 64 + mf * 16 + qrow;
        #pragma unroll
        for (int nf = 0; nf < 4; nf++) {
            const int ncol = nt * BN + wn * 32 + (nf >> 1) * 16 + (nf & 1) * 8 + 2 * qcol;
            float2* p0 = reinterpret_cast<float2*>(out + (size_t)mrow * Ndim + ncol);
            float2* p1 = reinterpret_cast<float2*>(out + (size_t)(mrow + 8) * Ndim + ncol);
            *p0 = make_float2(acc[mf][nf][0], acc[mf][nf][1]);
            *p1 = make_float2(acc[mf][nf][2], acc[mf][nf][3]);
        }
    }
}

// ============================ host side =====================================

extern "C" void kernel_launch(void* const* d_in, const int* in_sizes, int n_in,
                              void* d_out, int out_size)
{
    const float* x = (const float*)d_in[0];
    const float* w = (const float*)d_in[1];
    if (n_in >= 2 && in_sizes[0] == Ndim * Kdim && in_sizes[1] == Mdim * Kdim) {
        const float* t = x; x = w; w = t;   // defensive: metadata order swap
    }
    float* out = (float*)d_out;

    void* xh_p = nullptr;
    void* wt_p = nullptr;
    cudaGetSymbolAddress(&xh_p, g_Xh);
    cudaGetSymbolAddress(&wt_p, g_Wt);

    {
        int n4 = Mdim * Kdim / 4;
        xconv_kernel<<<(n4 + 255) / 256, 256>>>((const float4*)x, (uint2*)xh_p, n4);
    }
    wbin_kernel<<<dim3(Ndim / 32, Kdim / 32), dim3(32, 8)>>>(w, (__half*)wt_p);

    // unconditional every call: deterministic, no static guards (harness rule)
    cudaFuncSetAttribute(hgemm_kernel,
                         cudaFuncAttributeMaxDynamicSharedMemorySize, SMEM_SIZE);
    hgemm_kernel<<<(Mdim / BM) * (Ndim / BN), 256, SMEM_SIZE>>>(out);
}

// round 7
// speedup vs baseline: 1.1512x; 1.1512x over previous
#include <cuda_runtime.h>
#include <cuda_fp16.h>
#include <cstdint>
#include <cstddef>

// ============================================================================
// BinaryDense: out[8192,2048] = X[8192,2048](f32) @ binarize(W)[2048,2048]
//   binarize: w < 0 -> 0.0, w >= 0 -> 1.0   (exact in fp16)
//
// R4: passed 262us at 1 CTA/SM (128KB smem, 4 stages), ~50% mma issue eff.
// R5: 3 stages (96KB) -> 2 CTAs/SM (4 warps/SMSP), single barrier per chunk.
// ============================================================================

static constexpr int Mdim = 8192;
static constexpr int Ndim = 2048;
static constexpr int Kdim = 2048;

static constexpr int BM = 128;
static constexpr int BN = 128;
static constexpr int BK = 64;                 // fp16: 128B rows
static constexpr int STAGES = 3;
static constexpr int NCHUNKS = Kdim / BK;     // 32
static constexpr int A_BYTES = BM * BK * 2;   // 16 KB
static constexpr int B_BYTES = BN * BK * 2;   // 16 KB
static constexpr int STAGE_BYTES = A_BYTES + B_BYTES;       // 32 KB
static constexpr int SMEM_SIZE = STAGES * STAGE_BYTES;      // 96 KB -> 2 CTA/SM

// Allocation-free scratch (40 MB)
__device__ __align__(1024) __half g_Xh[(size_t)Mdim * Kdim]; // X fp16 [M,K]
__device__ __align__(1024) __half g_Wt[(size_t)Ndim * Kdim]; // bin(W)^T fp16 [N,K]

// ============================ helpers =======================================

__device__ __forceinline__ uint32_t smem_u32(const void* p) {
    uint32_t a;
    asm("{ .reg .u64 t; cvta.to.shared.u64 t, %1; cvt.u32.u64 %0, t; }"
        : "=r"(a) : "l"(p));
    return a;
}

__device__ __forceinline__ void cp_async16(uint32_t dst, const void* src) {
    asm volatile("cp.async.cg.shared.global [%0], [%1], 16;"
                 :: "r"(dst), "l"(src) : "memory");
}

__device__ __forceinline__ void cp_commit() {
    asm volatile("cp.async.commit_group;" ::: "memory");
}

template <int N>
__device__ __forceinline__ void cp_wait() {
    asm volatile("cp.async.wait_group %0;" :: "n"(N) : "memory");
}

__device__ __forceinline__ void ldsm_x4(uint32_t& r0, uint32_t& r1,
                                        uint32_t& r2, uint32_t& r3, uint32_t addr) {
    asm volatile("ldmatrix.sync.aligned.m8n8.x4.shared.b16 {%0,%1,%2,%3}, [%4];"
                 : "=r"(r0), "=r"(r1), "=r"(r2), "=r"(r3) : "r"(addr));
}

__device__ __forceinline__ void mma16816(float* c, const uint32_t* a,
                                         uint32_t b0, uint32_t b1) {
    asm volatile(
        "mma.sync.aligned.m16n8k16.row.col.f32.f16.f16.f32 "
        "{%0,%1,%2,%3}, {%4,%5,%6,%7}, {%8,%9}, {%0,%1,%2,%3};"
        : "+f"(c[0]), "+f"(c[1]), "+f"(c[2]), "+f"(c[3])
        : "r"(a[0]), "r"(a[1]), "r"(a[2]), "r"(a[3]), "r"(b0), "r"(b1));
}

// ============================ prepass kernels ===============================

__global__ void xconv_kernel(const float4* __restrict__ x, uint2* __restrict__ xh, int n4) {
    int i = blockIdx.x * blockDim.x + threadIdx.x;
    if (i < n4) {
        float4 v = x[i];
        __half2 a = __floats2half2_rn(v.x, v.y);
        __half2 b = __floats2half2_rn(v.z, v.w);
        uint2 u;
        u.x = *reinterpret_cast<const uint32_t*>(&a);
        u.y = *reinterpret_cast<const uint32_t*>(&b);
        xh[i] = u;
    }
}

// W [K,N] fp32 -> binarized W^T [N,K] fp16, tiled transpose
__global__ void wbin_kernel(const float* __restrict__ w, __half* __restrict__ wt) {
    __shared__ __half tile[32][33];
    int n0 = blockIdx.x * 32, k0 = blockIdx.y * 32;
    int tx = threadIdx.x, ty = threadIdx.y;
    #pragma unroll
    for (int i = 0; i < 32; i += 8) {
        float v = w[(size_t)(k0 + ty + i) * Ndim + (n0 + tx)];
        tile[ty + i][tx] = (v < 0.0f) ? __float2half(0.0f) : __float2half(1.0f);
    }
    __syncthreads();
    #pragma unroll
    for (int i = 0; i < 32; i += 8) {
        wt[(size_t)(n0 + ty + i) * Kdim + (k0 + tx)] = tile[tx][ty + i];
    }
}

// ============================ main GEMM kernel ==============================
//
// 256 threads = 8 warps as (wm 2) x (wn 4); warp tile 64m x 32n.
// Smem tiles: A [128][64] fp16 (128B rows), B [128][64] fp16 (row = n).
// 16B-granularity XOR swizzle: byte_off ^ ((row & 7) << 4)  (bits disjoint).
// Single barrier per chunk: iteration c loads chunk c+2 into stage (c-1)%3,
// whose last readers all passed this iteration's leading __syncthreads.

__device__ __forceinline__ void load_stage(
    int stage, int chunk, int mt, int nt, uint32_t sb, int tid)
{
    const uint32_t a_base = sb + stage * STAGE_BYTES;
    const uint32_t b_base = a_base + A_BYTES;
    const int m0 = mt * BM, n0 = nt * BN, k0 = chunk * BK;
    #pragma unroll
    for (int i = 0; i < 4; i++) {
        int id = tid + 256 * i;              // 0..1023
        int row = id >> 3, ch = id & 7;      // 8 x 16B chunks per 128B row
        uint32_t dst = a_base + row * 128 + ((ch * 16) ^ ((row & 7) << 4));
        cp_async16(dst, g_Xh + (size_t)(m0 + row) * Kdim + k0 + ch * 8);
    }
    #pragma unroll
    for (int i = 0; i < 4; i++) {
        int id = tid + 256 * i;
        int row = id >> 3, ch = id & 7;
        uint32_t dst = b_base + row * 128 + ((ch * 16) ^ ((row & 7) << 4));
        cp_async16(dst, g_Wt + (size_t)(n0 + row) * Kdim + k0 + ch * 8);
    }
}

__global__ void __launch_bounds__(256, 2) hgemm_kernel(float* __restrict__ out)
{
    extern __shared__ __align__(1024) char smem[];
    const uint32_t sb = smem_u32(smem);
    const int tid = threadIdx.x;
    const int wid = tid >> 5;
    const int lane = tid & 31;

    // 16 consecutive CTAs share the same A tile; all 16 B tiles (8 MB) stay
    // L2-resident -> HBM traffic ~ single pass of A + B + out.
    const int mt = blockIdx.x >> 4;
    const int nt = blockIdx.x & 15;

    const int wm = wid & 1;   // 0..1 -> 64-row halves
    const int wn = wid >> 1;  // 0..3 -> 32-col quarters

    float acc[4][4][4];
    #pragma unroll
    for (int i = 0; i < 4; i++)
        #pragma unroll
        for (int j = 0; j < 4; j++)
            #pragma unroll
            for (int q = 0; q < 4; q++) acc[i][j][q] = 0.0f;

    // ---- prologue: fill STAGES-1 stages ----
    #pragma unroll
    for (int s = 0; s < STAGES - 1; s++) {
        load_stage(s, s, mt, nt, sb, tid);
        cp_commit();
    }

    const int lrow = lane & 15;          // ldmatrix row within 16
    const int lhi  = lane >> 4;          // k-half selector (0/1)

    int s = 0;                           // compute stage for chunk c
    int ls = STAGES - 1;                 // load stage for chunk c+STAGES-1
    for (int c = 0; c < NCHUNKS; c++) {
        cp_wait<STAGES - 2>();           // stage s resident
        __syncthreads();                 // + all warps done with stage ls

        const int nc = c + (STAGES - 1);
        if (nc < NCHUNKS) load_stage(ls, nc, mt, nt, sb, tid);
        cp_commit();                     // one group per iteration (may be empty)

        const uint32_t a_base = sb + s * STAGE_BYTES;
        const uint32_t b_base = a_base + A_BYTES;

        #pragma unroll
        for (int kk = 0; kk < BK / 16; kk++) {
            // A fragments: 4 x m16 tiles
            uint32_t afr[4][4];
            #pragma unroll
            for (int mf = 0; mf < 4; mf++) {
                int row = wm * 64 + mf * 16 + lrow;
                uint32_t addr = a_base + row * 128 +
                                ((kk * 32 + lhi * 16) ^ ((row & 7) << 4));
                ldsm_x4(afr[mf][0], afr[mf][1], afr[mf][2], afr[mf][3], addr);
            }
            // B fragments: 2 x n16 tiles (each = 2 n8 mma frags)
            uint32_t bfr[2][4];
            #pragma unroll
            for (int p = 0; p < 2; p++) {
                int row = wn * 32 + p * 16 + lrow;   // row = n index
                uint32_t addr = b_base + row * 128 +
                                ((kk * 32 + lhi * 16) ^ ((row & 7) << 4));
                ldsm_x4(bfr[p][0], bfr[p][1], bfr[p][2], bfr[p][3], addr);
            }
            #pragma unroll
            for (int mf = 0; mf < 4; mf++) {
                #pragma unroll
                for (int p = 0; p < 2; p++) {
                    // n-frag 2p  : b = {bfr[p][0], bfr[p][2]}
                    // n-frag 2p+1: b = {bfr[p][1], bfr[p][3]}
                    mma16816(acc[mf][2 * p],     afr[mf], bfr[p][0], bfr[p][2]);
                    mma16816(acc[mf][2 * p + 1], afr[mf], bfr[p][1], bfr[p][3]);
                }
            }
        }
        s  = (s  + 1 == STAGES) ? 0 : s  + 1;
        ls = (ls + 1 == STAGES) ? 0 : ls + 1;
    }

    // ---- epilogue: direct float2 stores ----
    const int qrow = lane >> 2;          // 0..7
    const int qcol = lane & 3;           // 0..3
    #pragma unroll
    for (int mf = 0; mf < 4; mf++) {
        const int mrow = mt * BM + wm * 64 + mf * 16 + qrow;
        #pragma unroll
        for (int nf = 0; nf < 4; nf++) {
            const int ncol = nt * BN + wn * 32 + (nf >> 1) * 16 + (nf & 1) * 8 + 2 * qcol;
            float2* p0 = reinterpret_cast<float2*>(out + (size_t)mrow * Ndim + ncol);
            float2* p1 = reinterpret_cast<float2*>(out + (size_t)(mrow + 8) * Ndim + ncol);
            *p0 = make_float2(acc[mf][nf][0], acc[mf][nf][1]);
            *p1 = make_float2(acc[mf][nf][2], acc[mf][nf][3]);
        }
    }
}

// ============================ host side =====================================

extern "C" void kernel_launch(void* const* d_in, const int* in_sizes, int n_in,
                              void* d_out, int out_size)
{
    const float* x = (const float*)d_in[0];
    const float* w = (const float*)d_in[1];
    if (n_in >= 2 && in_sizes[0] == Ndim * Kdim && in_sizes[1] == Mdim * Kdim) {
        const float* t = x; x = w; w = t;   // defensive: metadata order swap
    }
    float* out = (float*)d_out;

    void* xh_p = nullptr;
    void* wt_p = nullptr;
    cudaGetSymbolAddress(&xh_p, g_Xh);
    cudaGetSymbolAddress(&wt_p, g_Wt);

    {
        int n4 = Mdim * Kdim / 4;
        xconv_kernel<<<(n4 + 255) / 256, 256>>>((const float4*)x, (uint2*)xh_p, n4);
    }
    wbin_kernel<<<dim3(Ndim / 32, Kdim / 32), dim3(32, 8)>>>(w, (__half*)wt_p);

    // unconditional every call: deterministic, no static guards (harness rule)
    cudaFuncSetAttribute(hgemm_kernel,
                         cudaFuncAttributeMaxDynamicSharedMemorySize, SMEM_SIZE);
    hgemm_kernel<<<(Mdim / BM) * (Ndim / BN), 256, SMEM_SIZE>>>(out);
}